// round 7
// baseline (speedup 1.0000x reference)
#include <cuda_runtime.h>
#include <cstdint>
#include <math.h>

// ---------------- problem constants ----------------
#define B_    2
#define CIN   64
#define COUT  64
#define DIN   64
#define DOUT  62
#define KTAPS 27
#define EPS_  1e-8f

#define NCHUNK 108                 // 27 taps x {x, dx} x 2 K-halves
#define ST_A   136                 // floats per A smem row, 128 + 8 pad
#define ST_B   36                  // floats per B smem row, 32 + 4 pad
#define A_BYTES (32 * ST_A * 4)    // 17408
#define B_BYTES (256 * ST_B * 4)   // 36864
#define STAGE   (A_BYTES + B_BYTES)   // 54272
#define NSTAGE  4
#define SMEM_DYN (NSTAGE * STAGE)     // 217088

// ---------------- device scratch ----------------
__device__ float g_wnv[B_ * COUT * CIN * KTAPS];
__device__ float g_dwv[B_ * COUT * CIN * KTAPS];
// A tiles: [b][kind][tap] x (64 k x 128 m) fp32(tf32-rounded), m contiguous
__device__ __align__(16) float g_A[B_ * 2 * KTAPS * 64 * 128];
// channel-last inputs [b][z][y][x][c], tf32-rounded, + pad for tap overreads
__device__ __align__(16) float g_xT [B_ * DIN * DIN * DIN * CIN + 16384];
__device__ __align__(16) float g_dxT[B_ * DIN * DIN * DIN * CIN + 16384];

// ---------------- helpers ----------------
__device__ __forceinline__ uint32_t smem_u32(const void* p) {
    uint32_t a;
    asm("{ .reg .u64 t; cvta.to.shared.u64 t, %1; cvt.u32.u64 %0, t; }" : "=r"(a) : "l"(p));
    return a;
}
__device__ __forceinline__ void cp_async16(uint32_t dst, const void* src) {
    asm volatile("cp.async.cg.shared.global [%0], [%1], 16;" :: "r"(dst), "l"(src) : "memory");
}
__device__ __forceinline__ uint32_t to_tf32(float v) {
    uint32_t u; asm("cvt.rna.tf32.f32 %0, %1;" : "=r"(u) : "f"(v)); return u;
}
__device__ __forceinline__ void mma_tf32(float* d, const uint32_t* a, const uint32_t* bfrag) {
    asm volatile(
        "mma.sync.aligned.m16n8k8.row.col.f32.tf32.tf32.f32 "
        "{%0,%1,%2,%3}, {%4,%5,%6,%7}, {%8,%9}, {%0,%1,%2,%3};"
        : "+f"(d[0]), "+f"(d[1]), "+f"(d[2]), "+f"(d[3])
        : "r"(a[0]), "r"(a[1]), "r"(a[2]), "r"(a[3]), "r"(bfrag[0]), "r"(bfrag[1]));
}

// ---------------------------------------------------------------------------
// Prep: style modulation + demodulation (validated round 2)
// ---------------------------------------------------------------------------
__global__ void prep_kernel(const float* __restrict__ s,
                            const float* __restrict__ style_weight,
                            const float* __restrict__ style_bias,
                            const float* __restrict__ weight)
{
    __shared__ float wsm[CIN * KTAPS];
    __shared__ float dwsm[CIN * KTAPS];
    __shared__ float red0[256];
    __shared__ float red1[256];

    const int b  = blockIdx.x >> 6;
    const int co = blockIdx.x & 63;
    const int tid = threadIdx.x;

    const float s0 = s[b * 2 + 0];
    const float s1 = s[b * 2 + 1];

    float sw2 = 0.f, swd = 0.f;
    for (int e = tid; e < CIN * KTAPS; e += 256) {
        const int ci = e / KTAPS;
        const float smod  = s0 * style_weight[ci * 2 + 0]
                          + s1 * style_weight[ci * 2 + 1]
                          + style_bias[ci];
        const float dsmod = style_weight[ci * 2 + 1];
        const float wt = weight[(co * CIN) * KTAPS + e];
        const float wv = wt * smod;
        const float dv = wt * dsmod;
        wsm[e]  = wv;
        dwsm[e] = dv;
        sw2 += wv * wv;
        swd += wv * dv;
    }
    red0[tid] = sw2;
    red1[tid] = swd;
    __syncthreads();
    for (int st = 128; st > 0; st >>= 1) {
        if (tid < st) { red0[tid] += red0[tid + st]; red1[tid] += red1[tid + st]; }
        __syncthreads();
    }
    const float norm  = sqrtf(red0[0] + EPS_);
    const float inv   = 1.0f / norm;
    const float dnorm = -red1[0] * inv * inv * inv;

    const size_t ob = (size_t)(b * COUT + co) * (CIN * KTAPS);
    for (int e = tid; e < CIN * KTAPS; e += 256) {
        g_wnv[ob + e] = wsm[e] * inv;
        g_dwv[ob + e] = dwsm[e] * inv + wsm[e] * dnorm;
    }
}

// ---------------------------------------------------------------------------
// Pack A tiles [k=ci 0..63][m=0..127], tf32-rounded.
//   kind 0 (B = x):  m<64 -> wn[co=m],  m>=64 -> dw[co=m-64]
//   kind 1 (B = dx): m<64 -> 0,         m>=64 -> wn[co=m-64]
// ---------------------------------------------------------------------------
__global__ void pack_kernel()
{
    const int blk  = blockIdx.x;
    const int t    = blk % KTAPS;
    const int kind = (blk / KTAPS) & 1;
    const int b    = blk / (2 * KTAPS);
    float* dst = g_A + (size_t)blk * (64 * 128);

    for (int e = threadIdx.x; e < 64 * 128; e += 256) {
        const int k = e >> 7;      // ci
        const int m = e & 127;
        float v = 0.f;
        if (kind == 0) {
            v = (m < 64)
              ? g_wnv[(size_t)(b * COUT + m)        * (CIN * KTAPS) + k * KTAPS + t]
              : g_dwv[(size_t)(b * COUT + (m - 64)) * (CIN * KTAPS) + k * KTAPS + t];
        } else if (m >= 64) {
            v = g_wnv[(size_t)(b * COUT + (m - 64)) * (CIN * KTAPS) + k * KTAPS + t];
        }
        dst[e] = __uint_as_float(to_tf32(v));
    }
}

// ---------------------------------------------------------------------------
// Transpose NCDHW -> [b][z][y][x][c], tf32-rounded.
// ---------------------------------------------------------------------------
__global__ void transpose_kernel(const float* __restrict__ x, const float* __restrict__ dx)
{
    __shared__ float tile[64][65];
    const int tx = threadIdx.x;            // 0..31
    const int ty = threadIdx.y;            // 0..7
    const int y = blockIdx.x, z = blockIdx.y, b = blockIdx.z;

    const size_t in_base = (size_t)(b * 64) * 262144 + (size_t)z * 4096 + (size_t)y * 64;
    const size_t r0 = (((size_t)(b * 64 + z)) * 64 + y) * 64;

    const float* srcs[2] = { x, dx };
    float* dsts[2] = { g_xT, g_dxT };

    for (int pass = 0; pass < 2; pass++) {
        const float* src = srcs[pass];
        float* dst = dsts[pass];
        __syncthreads();
        for (int c = ty; c < 64; c += 8) {
            tile[c][tx]      = src[in_base + (size_t)c * 262144 + tx];
            tile[c][tx + 32] = src[in_base + (size_t)c * 262144 + tx + 32];
        }
        __syncthreads();
        for (int xr = ty; xr < 64; xr += 8) {
            dst[(r0 + xr) * 64 + tx]      = __uint_as_float(to_tf32(tile[tx][xr]));
            dst[(r0 + xr) * 64 + tx + 32] = __uint_as_float(to_tf32(tile[tx + 32][xr]));
        }
    }
}

// ---------------------------------------------------------------------------
// Conv implicit-GEMM, warp-level mma.sync tf32.
// Grid (16 ytiles, 62 z, 2 b); 256 threads = 8 warps (2M x 4N), warp m64 x n64.
// 108 sub-chunks of K=32; 4-stage cp.async ring, one barrier per chunk:
//   wait_group(2)  -> my copies for chunk c landed (c+1, c+2 still pending)
//   __syncthreads  -> ALL threads' copies visible; all warps past compute(c-1)
//   stage(c+3)     -> into slot (c-1)&3, now safe to overwrite
//   compute(c)     -> slot c&3; staging issue drains under tensor work
// c < 54: B = x;  c >= 54: B = dx (A rows 0..63 zero -> wm==0 warps skip).
// ---------------------------------------------------------------------------
__global__ __launch_bounds__(256, 1) void conv_mma_kernel(
    const float* __restrict__ bias, float* __restrict__ out)
{
    extern __shared__ __align__(16) float smem[];
    const uint32_t sb = smem_u32(smem);

    const int tid = threadIdx.x;
    const int wid = tid >> 5;
    const int lid = tid & 31;
    const int wm  = wid >> 2;          // M tile 0..1 (rows wm*64..)
    const int wn  = wid & 3;           // N tile 0..3 (cols wn*64..)
    const int g   = lid >> 2;          // group id 0..7
    const int ct  = lid & 3;           // thread-in-group

    const int y0 = blockIdx.x * 4;
    const int z0 = blockIdx.y;
    const int b  = blockIdx.z;

    float acc[4][8][4];
    #pragma unroll
    for (int mi = 0; mi < 4; ++mi)
        #pragma unroll
        for (int ni = 0; ni < 8; ++ni)
            #pragma unroll
            for (int j = 0; j < 4; ++j) acc[mi][ni][j] = 0.f;

    // ---- staging helper: sub-chunk c into ring slot s ----
    auto stage = [&](int c, int s) {
        const int kind = (c >= 54) ? 1 : 0;
        const int r    = c - kind * 54;
        const int t    = r >> 1;
        const int h    = r & 1;                    // K half
        // A: 32 k-rows x 128 m
        const float4* srcA = (const float4*)(g_A
            + (size_t)((b * 2 + kind) * KTAPS + t) * (64 * 128) + (size_t)h * 32 * 128);
        const uint32_t dA = sb + s * STAGE;
        #pragma unroll
        for (int it = 0; it < 4; ++it) {
            const int i = tid + it * 256;          // 0..1023
            cp_async16(dA + (i >> 5) * (ST_A * 4) + (i & 31) * 16, srcA + i);
        }
        // B: 256 n-rows x 32 channels
        const float* srcT = kind ? g_dxT : g_xT;
        const int dz  = t / 9;
        const int dyy = (t % 9) / 3;
        const int dxx = t % 3;
        const int rb  = ((b * 64 + (z0 + dz)) * 64 + (y0 + dyy)) * 64 + dxx;
        const uint32_t dB = sb + s * STAGE + A_BYTES;
        #pragma unroll
        for (int it = 0; it < 8; ++it) {
            const int i  = tid + it * 256;         // 0..2047
            const int n  = i >> 3;
            const int k4 = i & 7;
            const int rr = rb + (n >> 6) * 64 + (n & 63);
            cp_async16(dB + n * (ST_B * 4) + k4 * 16,
                       srcT + (size_t)rr * 64 + h * 32 + k4 * 4);
        }
    };

    // ---- prologue: fill 3 of 4 stages ----
    stage(0, 0); asm volatile("cp.async.commit_group;" ::: "memory");
    stage(1, 1); asm volatile("cp.async.commit_group;" ::: "memory");
    stage(2, 2); asm volatile("cp.async.commit_group;" ::: "memory");

    const int m_base = wm * 64;
    const int n_base = wn * 64;

    for (int c = 0; c < NCHUNK; ++c) {
        // my copies for chunk c done (c+1, c+2 remain pending)
        asm volatile("cp.async.wait_group %0;" :: "n"(NSTAGE - 2) : "memory");
        // all threads' copies visible; all warps finished compute(c-1)
        __syncthreads();
        if (c + 3 < NCHUNK) stage(c + 3, (c + 3) & 3);
        asm volatile("cp.async.commit_group;" ::: "memory");

        const int s = c & 3;
        const bool active = !(c >= 54 && wm == 0);
        if (active) {
            const uint32_t* As = (const uint32_t*)((const char*)smem + s * STAGE);
            const uint32_t* Bs = (const uint32_t*)((const char*)smem + s * STAGE + A_BYTES);
            #pragma unroll
            for (int ks = 0; ks < 4; ++ks) {
                uint32_t a[4][4];
                #pragma unroll
                for (int mi = 0; mi < 4; ++mi) {
                    const int m0 = m_base + mi * 16 + g;
                    a[mi][0] = As[(ks * 8 + ct)     * ST_A + m0];
                    a[mi][1] = As[(ks * 8 + ct)     * ST_A + m0 + 8];
                    a[mi][2] = As[(ks * 8 + ct + 4) * ST_A + m0];
                    a[mi][3] = As[(ks * 8 + ct + 4) * ST_A + m0 + 8];
                }
                uint32_t bf[8][2];
                #pragma unroll
                for (int ni = 0; ni < 8; ++ni) {
                    const int n0 = n_base + ni * 8 + g;
                    bf[ni][0] = Bs[n0 * ST_B + ks * 8 + ct];
                    bf[ni][1] = Bs[n0 * ST_B + ks * 8 + ct + 4];
                }
                #pragma unroll
                for (int mi = 0; mi < 4; ++mi)
                    #pragma unroll
                    for (int ni = 0; ni < 8; ++ni)
                        mma_tf32(acc[mi][ni], a[mi], bf[ni]);
            }
        }
    }

    // ---- epilogue ----
    const size_t NOUT   = (size_t)DOUT * DOUT * DOUT;
    const size_t dy_off = (size_t)B_ * COUT * NOUT;

    #pragma unroll
    for (int mi = 0; mi < 4; ++mi) {
        #pragma unroll
        for (int h = 0; h < 2; ++h) {
            const int m  = m_base + mi * 16 + h * 8 + g;
            const bool isy = (m < 64);
            const int co = m & 63;
            const float bv = isy ? bias[co] : 0.f;
            const size_t outadd = isy ? 0 : dy_off;
            const size_t ob = ((size_t)(b * COUT + co) * DOUT + z0) * DOUT;
            #pragma unroll
            for (int ni = 0; ni < 8; ++ni) {
                const int n  = n_base + ni * 8 + ct * 2;
                const int yo = y0 + (n >> 6);
                const int xo = n & 63;
                if (yo < DOUT) {
                    const size_t idx = (ob + yo) * DOUT + xo;
                    if (xo < DOUT) {
                        out[outadd + idx]     = acc[mi][ni][h * 2 + 0] + bv;
                        out[outadd + idx + 1] = acc[mi][ni][h * 2 + 1] + bv;  // xo even => xo+1 valid
                    }
                }
            }
        }
    }
}

// ---------------------------------------------------------------------------
// Launch. Inputs: x, s, dx, style_weight, style_bias, weight, bias.
// Output: concat(y, dy) fp32.
// ---------------------------------------------------------------------------
extern "C" void kernel_launch(void* const* d_in, const int* in_sizes, int n_in,
                              void* d_out, int out_size)
{
    const float* x    = (const float*)d_in[0];
    const float* s    = (const float*)d_in[1];
    const float* dx   = (const float*)d_in[2];
    const float* sw   = (const float*)d_in[3];
    const float* sb   = (const float*)d_in[4];
    const float* w    = (const float*)d_in[5];
    const float* bias = (const float*)d_in[6];
    float* out = (float*)d_out;

    cudaFuncSetAttribute(conv_mma_kernel, cudaFuncAttributeMaxDynamicSharedMemorySize, SMEM_DYN);

    prep_kernel<<<B_ * COUT, 256>>>(s, sw, sb, w);
    pack_kernel<<<B_ * 2 * KTAPS, 256>>>();
    transpose_kernel<<<dim3(64, 64, B_), dim3(32, 8)>>>(x, dx);
    conv_mma_kernel<<<dim3(16, 62, B_), 256, SMEM_DYN>>>(bias, out);
}

// round 8
// speedup vs baseline: 2.1051x; 2.1051x over previous
#include <cuda_runtime.h>
#include <cuda_fp16.h>
#include <cstdint>
#include <math.h>

// ---------------- problem constants ----------------
#define B_    2
#define CIN   64
#define COUT  64
#define DIN   64
#define DOUT  62
#define KTAPS 27
#define EPS_  1e-8f

#define NCHUNK 54                  // 27 taps x {x, dx}, K=64 each
#define A_BYTES 16384              // 128 m x 64 k fp16
#define B_BYTES 32768              // 256 n x 64 k fp16
#define STAGE   (A_BYTES + B_BYTES)   // 49152
#define NSTAGE  4
#define SMEM_DYN (NSTAGE * STAGE)     // 196608

// ---------------- device scratch ----------------
__device__ float g_wnv[B_ * COUT * CIN * KTAPS];
__device__ float g_dwv[B_ * COUT * CIN * KTAPS];
// A tiles fp16, pre-swizzled [b][kind][tap] x (128 m x 64 k), row=128B,
// 16B-chunk c stored at c ^ (m&7)
__device__ __align__(16) __half g_Ah[B_ * 2 * KTAPS * 128 * 64];
// channel-last fp16 inputs [b][z][y][x][c] (row = 64 ch = 128B), + overread pad
__device__ __align__(16) __half g_xTh [B_ * DIN * DIN * DIN * CIN + 32768];
__device__ __align__(16) __half g_dxTh[B_ * DIN * DIN * DIN * CIN + 32768];

// ---------------- helpers ----------------
__device__ __forceinline__ uint32_t smem_u32(const void* p) {
    uint32_t a;
    asm("{ .reg .u64 t; cvta.to.shared.u64 t, %1; cvt.u32.u64 %0, t; }" : "=r"(a) : "l"(p));
    return a;
}
__device__ __forceinline__ void cp_async16(uint32_t dst, const void* src) {
    asm volatile("cp.async.cg.shared.global [%0], [%1], 16;" :: "r"(dst), "l"(src) : "memory");
}
#define LDMATRIX_X4(r0, r1, r2, r3, addr) \
    asm volatile("ldmatrix.sync.aligned.m8n8.x4.shared.b16 {%0,%1,%2,%3}, [%4];" \
        : "=r"(r0), "=r"(r1), "=r"(r2), "=r"(r3) : "r"(addr))

__device__ __forceinline__ void mma_f16(float* d, const uint32_t* a, const uint32_t* b2) {
    asm volatile(
        "mma.sync.aligned.m16n8k16.row.col.f32.f16.f16.f32 "
        "{%0,%1,%2,%3}, {%4,%5,%6,%7}, {%8,%9}, {%0,%1,%2,%3};"
        : "+f"(d[0]), "+f"(d[1]), "+f"(d[2]), "+f"(d[3])
        : "r"(a[0]), "r"(a[1]), "r"(a[2]), "r"(a[3]), "r"(b2[0]), "r"(b2[1]));
}

// ---------------------------------------------------------------------------
// Prep: style modulation + demodulation (validated round 2)
// ---------------------------------------------------------------------------
__global__ void prep_kernel(const float* __restrict__ s,
                            const float* __restrict__ style_weight,
                            const float* __restrict__ style_bias,
                            const float* __restrict__ weight)
{
    __shared__ float wsm[CIN * KTAPS];
    __shared__ float dwsm[CIN * KTAPS];
    __shared__ float red0[256];
    __shared__ float red1[256];

    const int b  = blockIdx.x >> 6;
    const int co = blockIdx.x & 63;
    const int tid = threadIdx.x;

    const float s0 = s[b * 2 + 0];
    const float s1 = s[b * 2 + 1];

    float sw2 = 0.f, swd = 0.f;
    for (int e = tid; e < CIN * KTAPS; e += 256) {
        const int ci = e / KTAPS;
        const float smod  = s0 * style_weight[ci * 2 + 0]
                          + s1 * style_weight[ci * 2 + 1]
                          + style_bias[ci];
        const float dsmod = style_weight[ci * 2 + 1];
        const float wt = weight[(co * CIN) * KTAPS + e];
        const float wv = wt * smod;
        const float dv = wt * dsmod;
        wsm[e]  = wv;
        dwsm[e] = dv;
        sw2 += wv * wv;
        swd += wv * dv;
    }
    red0[tid] = sw2;
    red1[tid] = swd;
    __syncthreads();
    for (int st = 128; st > 0; st >>= 1) {
        if (tid < st) { red0[tid] += red0[tid + st]; red1[tid] += red1[tid + st]; }
        __syncthreads();
    }
    const float norm  = sqrtf(red0[0] + EPS_);
    const float inv   = 1.0f / norm;
    const float dnorm = -red1[0] * inv * inv * inv;

    const size_t ob = (size_t)(b * COUT + co) * (CIN * KTAPS);
    for (int e = tid; e < CIN * KTAPS; e += 256) {
        g_wnv[ob + e] = wsm[e] * inv;
        g_dwv[ob + e] = dwsm[e] * inv + wsm[e] * dnorm;
    }
}

// ---------------------------------------------------------------------------
// Pack A tiles: fp16, [m=128][k=64] rows of 128B; 16B chunk (k>>3) stored at
// (k>>3) ^ (m&7)  ->  ldmatrix conflict-free.
//   kind 0 (B = x):  m<64 -> wn[co=m],  m>=64 -> dw[co=m-64]
//   kind 1 (B = dx): m<64 -> 0,         m>=64 -> wn[co=m-64]
// ---------------------------------------------------------------------------
__global__ void pack_kernel()
{
    const int blk  = blockIdx.x;
    const int t    = blk % KTAPS;
    const int kind = (blk / KTAPS) & 1;
    const int b    = blk / (2 * KTAPS);
    char* dst = (char*)g_Ah + (size_t)blk * A_BYTES;

    for (int e = threadIdx.x; e < 128 * 64; e += 256) {
        const int m = e >> 6;
        const int k = e & 63;
        float v = 0.f;
        if (kind == 0) {
            v = (m < 64)
              ? g_wnv[(size_t)(b * COUT + m)        * (CIN * KTAPS) + k * KTAPS + t]
              : g_dwv[(size_t)(b * COUT + (m - 64)) * (CIN * KTAPS) + k * KTAPS + t];
        } else if (m >= 64) {
            v = g_wnv[(size_t)(b * COUT + (m - 64)) * (CIN * KTAPS) + k * KTAPS + t];
        }
        const uint32_t off = (uint32_t)(m * 128 + (((k >> 3) ^ (m & 7)) << 4) + (k & 7) * 2);
        *(__half*)(dst + off) = __float2half_rn(v);
    }
}

// ---------------------------------------------------------------------------
// Transpose NCDHW -> fp16 channel-last [b][z][y][x][c].
// ---------------------------------------------------------------------------
__global__ void transpose_kernel(const float* __restrict__ x, const float* __restrict__ dx)
{
    __shared__ float tile[64][65];
    const int tx = threadIdx.x;            // 0..31
    const int ty = threadIdx.y;            // 0..7
    const int y = blockIdx.x, z = blockIdx.y, b = blockIdx.z;

    const size_t in_base = (size_t)(b * 64) * 262144 + (size_t)z * 4096 + (size_t)y * 64;
    const size_t r0 = (((size_t)(b * 64 + z)) * 64 + y) * 64;

    const float* srcs[2] = { x, dx };
    __half* dsts[2] = { g_xTh, g_dxTh };

    for (int pass = 0; pass < 2; pass++) {
        const float* src = srcs[pass];
        __half* dst = dsts[pass];
        __syncthreads();
        for (int c = ty; c < 64; c += 8) {
            tile[c][tx]      = src[in_base + (size_t)c * 262144 + tx];
            tile[c][tx + 32] = src[in_base + (size_t)c * 262144 + tx + 32];
        }
        __syncthreads();
        for (int xr = ty; xr < 64; xr += 8) {
            dst[(r0 + xr) * 64 + tx]      = __float2half_rn(tile[tx][xr]);
            dst[(r0 + xr) * 64 + tx + 32] = __float2half_rn(tile[tx + 32][xr]);
        }
    }
}

// ---------------------------------------------------------------------------
// Conv implicit-GEMM, fp16 mma.sync m16n8k16 + ldmatrix.
// Grid (16 ytiles, 62 z, 2 b); 256 threads = 8 warps (2M x 4N), warp m64 x n64.
// 54 chunks of K=64; 4-stage cp.async ring, one barrier per chunk (R7 order).
// A smem: [m=128][k=64] fp16 rows 128B, chunk swizzle ^(m&7).
// B smem: [n=256][k=64] fp16 rows 128B, chunk swizzle ^(n&7).
// c < 27: B = x;  c >= 27: B = dx (A rows 0..63 zero -> wm==0 warps skip).
// ---------------------------------------------------------------------------
__global__ __launch_bounds__(256, 1) void conv_mma_kernel(
    const float* __restrict__ bias, float* __restrict__ out)
{
    extern __shared__ __align__(16) char smem[];
    const uint32_t sb = smem_u32(smem);

    const int tid = threadIdx.x;
    const int wid = tid >> 5;
    const int lid = tid & 31;
    const int wm  = wid >> 2;          // M tile 0..1 (rows wm*64..)
    const int wn  = wid & 3;           // N tile 0..3 (cols wn*64..)
    const int g   = lid >> 2;          // 0..7
    const int ct  = lid & 3;           // 0..3

    const int y0 = blockIdx.x * 4;
    const int z0 = blockIdx.y;
    const int b  = blockIdx.z;

    float acc[4][8][4];
    #pragma unroll
    for (int mi = 0; mi < 4; ++mi)
        #pragma unroll
        for (int ni = 0; ni < 8; ++ni)
            #pragma unroll
            for (int j = 0; j < 4; ++j) acc[mi][ni][j] = 0.f;

    // ---- per-thread ldmatrix row indices (k-part added per ks) ----
    // A x4: matrices {m0-7/k0-7, m8-15/k0-7, m0-7/k8-15, m8-15/k8-15}
    const int a_m  = wm * 64 + (lid & 7) + ((lid >> 3) & 1) * 8;  // + mi*16
    const int a_kq = (lid >> 4) & 1;                               // k-chunk half (8k units)
    // B x4: matrices {n0-7/k0-7, n0-7/k8-15, n8-15/k0-7, n8-15/k8-15}
    const int b_n  = wn * 64 + (lid & 7) + ((lid >> 4) & 1) * 8;  // + q*16
    const int b_kq = (lid >> 3) & 1;

    // ---- staging helper: chunk c into ring slot s ----
    auto stage = [&](int c, int s) {
        const int kind = (c >= KTAPS) ? 1 : 0;
        const int t    = c - kind * KTAPS;
        // A: pre-swizzled 16 KB tile, linear copy
        const char* srcA = (const char*)g_Ah + (size_t)((b * 2 + kind) * KTAPS + t) * A_BYTES;
        const uint32_t dA = sb + s * STAGE;
        #pragma unroll
        for (int it = 0; it < 4; ++it) {
            const int i = tid + it * 256;          // 0..1023
            cp_async16(dA + i * 16, srcA + i * 16);
        }
        // B: im2col gather, 2048 x 16B (8 channels each)
        const __half* srcT = kind ? g_dxTh : g_xTh;
        const int dz  = t / 9;
        const int dyy = (t % 9) / 3;
        const int dxx = t % 3;
        const int rb  = ((b * 64 + (z0 + dz)) * 64 + (y0 + dyy)) * 64 + dxx;
        const uint32_t dB = sb + s * STAGE + A_BYTES;
        #pragma unroll
        for (int it = 0; it < 8; ++it) {
            const int i  = tid + it * 256;         // 0..2047
            const int n  = i >> 3;
            const int c8 = i & 7;
            const int rr = rb + (n >> 6) * 64 + (n & 63);
            cp_async16(dB + n * 128 + ((c8 ^ (n & 7)) << 4),
                       (const char*)srcT + (size_t)rr * 128 + c8 * 16);
        }
    };

    // ---- prologue: fill 3 of 4 stages ----
    stage(0, 0); asm volatile("cp.async.commit_group;" ::: "memory");
    stage(1, 1); asm volatile("cp.async.commit_group;" ::: "memory");
    stage(2, 2); asm volatile("cp.async.commit_group;" ::: "memory");

    for (int c = 0; c < NCHUNK; ++c) {
        // my copies for chunk c done (c+1, c+2 remain pending)
        asm volatile("cp.async.wait_group %0;" :: "n"(NSTAGE - 2) : "memory");
        // all threads' copies visible; all warps finished compute(c-1)
        __syncthreads();
        if (c + 3 < NCHUNK) stage(c + 3, (c + 3) & 3);
        asm volatile("cp.async.commit_group;" ::: "memory");

        const int s = c & 3;
        const bool active = !(c >= KTAPS && wm == 0);
        if (active) {
            const uint32_t As = sb + s * STAGE;
            const uint32_t Bs = As + A_BYTES;
            #pragma unroll
            for (int ks = 0; ks < 4; ++ks) {          // K = 4 x 16
                const int kq_a = ks * 2 + a_kq;       // 8k-chunk index 0..7
                const int kq_b = ks * 2 + b_kq;
                uint32_t a[4][4];
                #pragma unroll
                for (int mi = 0; mi < 4; ++mi) {
                    const int m = a_m + mi * 16;
                    LDMATRIX_X4(a[mi][0], a[mi][1], a[mi][2], a[mi][3],
                                As + m * 128 + ((kq_a ^ (m & 7)) << 4));
                }
                uint32_t bq[4][4];
                #pragma unroll
                for (int q = 0; q < 4; ++q) {
                    const int n = b_n + q * 16;
                    LDMATRIX_X4(bq[q][0], bq[q][1], bq[q][2], bq[q][3],
                                Bs + n * 128 + ((kq_b ^ (n & 7)) << 4));
                }
                #pragma unroll
                for (int mi = 0; mi < 4; ++mi)
                    #pragma unroll
                    for (int q = 0; q < 4; ++q) {
                        mma_f16(acc[mi][2 * q + 0], a[mi], &bq[q][0]);
                        mma_f16(acc[mi][2 * q + 1], a[mi], &bq[q][2]);
                    }
            }
        }
    }

    // ---- epilogue (D fragment layout identical to tf32 path) ----
    const size_t NOUT   = (size_t)DOUT * DOUT * DOUT;
    const size_t dy_off = (size_t)B_ * COUT * NOUT;
    const int m_base = wm * 64;
    const int n_base = wn * 64;

    #pragma unroll
    for (int mi = 0; mi < 4; ++mi) {
        #pragma unroll
        for (int h = 0; h < 2; ++h) {
            const int m  = m_base + mi * 16 + h * 8 + g;
            const bool isy = (m < 64);
            const int co = m & 63;
            const float bv = isy ? bias[co] : 0.f;
            const size_t outadd = isy ? 0 : dy_off;
            const size_t ob = ((size_t)(b * COUT + co) * DOUT + z0) * DOUT;
            #pragma unroll
            for (int ni = 0; ni < 8; ++ni) {
                const int n  = n_base + ni * 8 + ct * 2;
                const int yo = y0 + (n >> 6);
                const int xo = n & 63;
                if (yo < DOUT) {
                    const size_t idx = (ob + yo) * DOUT + xo;
                    if (xo < DOUT) {
                        out[outadd + idx]     = acc[mi][ni][h * 2 + 0] + bv;
                        out[outadd + idx + 1] = acc[mi][ni][h * 2 + 1] + bv;  // xo even => xo+1 valid
                    }
                }
            }
        }
    }
}

// ---------------------------------------------------------------------------
// Launch. Inputs: x, s, dx, style_weight, style_bias, weight, bias.
// Output: concat(y, dy) fp32.
// ---------------------------------------------------------------------------
extern "C" void kernel_launch(void* const* d_in, const int* in_sizes, int n_in,
                              void* d_out, int out_size)
{
    const float* x    = (const float*)d_in[0];
    const float* s    = (const float*)d_in[1];
    const float* dx   = (const float*)d_in[2];
    const float* sw   = (const float*)d_in[3];
    const float* sb   = (const float*)d_in[4];
    const float* w    = (const float*)d_in[5];
    const float* bias = (const float*)d_in[6];
    float* out = (float*)d_out;

    cudaFuncSetAttribute(conv_mma_kernel, cudaFuncAttributeMaxDynamicSharedMemorySize, SMEM_DYN);

    prep_kernel<<<B_ * COUT, 256>>>(s, sw, sb, w);
    pack_kernel<<<B_ * 2 * KTAPS, 256>>>();
    transpose_kernel<<<dim3(64, 64, B_), dim3(32, 8)>>>(x, dx);
    conv_mma_kernel<<<dim3(16, 62, B_), 256, SMEM_DYN>>>(bias, out);
}

// round 9
// speedup vs baseline: 2.1273x; 1.0106x over previous
#include <cuda_runtime.h>
#include <cuda_fp16.h>
#include <cstdint>
#include <math.h>

// ---------------- problem constants ----------------
#define B_    2
#define CIN   64
#define COUT  64
#define DIN   64
#define DOUT  62
#define KTAPS 27
#define EPS_  1e-8f

#define NCHUNK 54                  // 27 taps x {x, dx}, K=64 each
#define A_BYTES 16384              // 128 m x 64 k fp16
#define B_BYTES 32768              // 256 n x 64 k fp16
#define STAGE   (A_BYTES + B_BYTES)   // 49152
#define NSTAGE  4
#define SMEM_DYN (NSTAGE * STAGE)     // 196608

// ---------------- device scratch ----------------
__device__ float g_wnv[B_ * COUT * CIN * KTAPS];
__device__ float g_dwv[B_ * COUT * CIN * KTAPS];
// A tiles fp16, pre-swizzled [b][kind][tap] x (128 m x 64 k), row=128B,
// 16B-chunk c stored at c ^ (m&7)
__device__ __align__(16) __half g_Ah[B_ * 2 * KTAPS * 128 * 64];
// channel-last fp16 inputs [b][z][y][x][c] (row = 64 ch = 128B), + overread pad
__device__ __align__(16) __half g_xTh [B_ * DIN * DIN * DIN * CIN + 32768];
__device__ __align__(16) __half g_dxTh[B_ * DIN * DIN * DIN * CIN + 32768];

// ---------------- helpers ----------------
__device__ __forceinline__ uint32_t smem_u32(const void* p) {
    uint32_t a;
    asm("{ .reg .u64 t; cvta.to.shared.u64 t, %1; cvt.u32.u64 %0, t; }" : "=r"(a) : "l"(p));
    return a;
}
__device__ __forceinline__ void cp_async16(uint32_t dst, const void* src) {
    asm volatile("cp.async.cg.shared.global [%0], [%1], 16;" :: "r"(dst), "l"(src) : "memory");
}
#define LDMATRIX_X4(r0, r1, r2, r3, addr) \
    asm volatile("ldmatrix.sync.aligned.m8n8.x4.shared.b16 {%0,%1,%2,%3}, [%4];" \
        : "=r"(r0), "=r"(r1), "=r"(r2), "=r"(r3) : "r"(addr))

__device__ __forceinline__ void mma_f16(float* d, const uint32_t* a, const uint32_t* b2) {
    asm volatile(
        "mma.sync.aligned.m16n8k16.row.col.f32.f16.f16.f32 "
        "{%0,%1,%2,%3}, {%4,%5,%6,%7}, {%8,%9}, {%0,%1,%2,%3};"
        : "+f"(d[0]), "+f"(d[1]), "+f"(d[2]), "+f"(d[3])
        : "r"(a[0]), "r"(a[1]), "r"(a[2]), "r"(a[3]), "r"(b2[0]), "r"(b2[1]));
}

// ---------------------------------------------------------------------------
// Prep: style modulation + demodulation (validated round 2)
// ---------------------------------------------------------------------------
__global__ void prep_kernel(const float* __restrict__ s,
                            const float* __restrict__ style_weight,
                            const float* __restrict__ style_bias,
                            const float* __restrict__ weight)
{
    __shared__ float wsm[CIN * KTAPS];
    __shared__ float dwsm[CIN * KTAPS];
    __shared__ float red0[256];
    __shared__ float red1[256];

    const int b  = blockIdx.x >> 6;
    const int co = blockIdx.x & 63;
    const int tid = threadIdx.x;

    const float s0 = s[b * 2 + 0];
    const float s1 = s[b * 2 + 1];

    float sw2 = 0.f, swd = 0.f;
    for (int e = tid; e < CIN * KTAPS; e += 256) {
        const int ci = e / KTAPS;
        const float smod  = s0 * style_weight[ci * 2 + 0]
                          + s1 * style_weight[ci * 2 + 1]
                          + style_bias[ci];
        const float dsmod = style_weight[ci * 2 + 1];
        const float wt = weight[(co * CIN) * KTAPS + e];
        const float wv = wt * smod;
        const float dv = wt * dsmod;
        wsm[e]  = wv;
        dwsm[e] = dv;
        sw2 += wv * wv;
        swd += wv * dv;
    }
    red0[tid] = sw2;
    red1[tid] = swd;
    __syncthreads();
    for (int st = 128; st > 0; st >>= 1) {
        if (tid < st) { red0[tid] += red0[tid + st]; red1[tid] += red1[tid + st]; }
        __syncthreads();
    }
    const float norm  = sqrtf(red0[0] + EPS_);
    const float inv   = 1.0f / norm;
    const float dnorm = -red1[0] * inv * inv * inv;

    const size_t ob = (size_t)(b * COUT + co) * (CIN * KTAPS);
    for (int e = tid; e < CIN * KTAPS; e += 256) {
        g_wnv[ob + e] = wsm[e] * inv;
        g_dwv[ob + e] = dwsm[e] * inv + wsm[e] * dnorm;
    }
}

// ---------------------------------------------------------------------------
// Pack A tiles: fp16, [m=128][k=64] rows of 128B; 16B chunk (k>>3) stored at
// (k>>3) ^ (m&7)  ->  ldmatrix conflict-free.
//   kind 0 (B = x):  m<64 -> wn[co=m],  m>=64 -> dw[co=m-64]
//   kind 1 (B = dx): m<64 -> 0,         m>=64 -> wn[co=m-64]
// ---------------------------------------------------------------------------
__global__ void pack_kernel()
{
    const int blk  = blockIdx.x;
    const int t    = blk % KTAPS;
    const int kind = (blk / KTAPS) & 1;
    const int b    = blk / (2 * KTAPS);
    char* dst = (char*)g_Ah + (size_t)blk * A_BYTES;

    for (int e = threadIdx.x; e < 128 * 64; e += 256) {
        const int m = e >> 6;
        const int k = e & 63;
        float v = 0.f;
        if (kind == 0) {
            v = (m < 64)
              ? g_wnv[(size_t)(b * COUT + m)        * (CIN * KTAPS) + k * KTAPS + t]
              : g_dwv[(size_t)(b * COUT + (m - 64)) * (CIN * KTAPS) + k * KTAPS + t];
        } else if (m >= 64) {
            v = g_wnv[(size_t)(b * COUT + (m - 64)) * (CIN * KTAPS) + k * KTAPS + t];
        }
        const uint32_t off = (uint32_t)(m * 128 + (((k >> 3) ^ (m & 7)) << 4) + (k & 7) * 2);
        *(__half*)(dst + off) = __float2half_rn(v);
    }
}

// ---------------------------------------------------------------------------
// Transpose NCDHW -> fp16 channel-last [b][z][y][x][c].
// ---------------------------------------------------------------------------
__global__ void transpose_kernel(const float* __restrict__ x, const float* __restrict__ dx)
{
    __shared__ float tile[64][65];
    const int tx = threadIdx.x;            // 0..31
    const int ty = threadIdx.y;            // 0..7
    const int y = blockIdx.x, z = blockIdx.y, b = blockIdx.z;

    const size_t in_base = (size_t)(b * 64) * 262144 + (size_t)z * 4096 + (size_t)y * 64;
    const size_t r0 = (((size_t)(b * 64 + z)) * 64 + y) * 64;

    const float* srcs[2] = { x, dx };
    __half* dsts[2] = { g_xTh, g_dxTh };

    for (int pass = 0; pass < 2; pass++) {
        const float* src = srcs[pass];
        __half* dst = dsts[pass];
        __syncthreads();
        for (int c = ty; c < 64; c += 8) {
            tile[c][tx]      = src[in_base + (size_t)c * 262144 + tx];
            tile[c][tx + 32] = src[in_base + (size_t)c * 262144 + tx + 32];
        }
        __syncthreads();
        for (int xr = ty; xr < 64; xr += 8) {
            dst[(r0 + xr) * 64 + tx]      = __float2half_rn(tile[tx][xr]);
            dst[(r0 + xr) * 64 + tx + 32] = __float2half_rn(tile[tx + 32][xr]);
        }
    }
}

// ---------------------------------------------------------------------------
// Conv implicit-GEMM, fp16 mma.sync m16n8k16 + ldmatrix.
// Grid (16 ytiles, 62 z, 2 b); 512 threads = 16 warps (4M x 4N),
// warp tile m32 x n64 -> 4 warps per SMSP for ldmatrix latency hiding.
// 54 chunks of K=64; 4-stage cp.async ring, one barrier per chunk (R7 order).
// A smem: [m=128][k=64] fp16 rows 128B, chunk swizzle ^(m&7).
// B smem: [n=256][k=64] fp16 rows 128B, chunk swizzle ^(n&7).
// c < 27: B = x;  c >= 27: B = dx (A rows 0..63 zero -> wm<2 warps skip).
// ---------------------------------------------------------------------------
__global__ __launch_bounds__(512, 1) void conv_mma_kernel(
    const float* __restrict__ bias, float* __restrict__ out)
{
    extern __shared__ __align__(16) char smem[];
    const uint32_t sb = smem_u32(smem);

    const int tid = threadIdx.x;
    const int wid = tid >> 5;
    const int lid = tid & 31;
    const int wm  = wid >> 2;          // M tile 0..3 (rows wm*32..)
    const int wn  = wid & 3;           // N tile 0..3 (cols wn*64..)
    const int g   = lid >> 2;          // 0..7
    const int ct  = lid & 3;           // 0..3

    const int y0 = blockIdx.x * 4;
    const int z0 = blockIdx.y;
    const int b  = blockIdx.z;

    float acc[2][8][4];
    #pragma unroll
    for (int mi = 0; mi < 2; ++mi)
        #pragma unroll
        for (int ni = 0; ni < 8; ++ni)
            #pragma unroll
            for (int j = 0; j < 4; ++j) acc[mi][ni][j] = 0.f;

    // ---- per-thread ldmatrix row indices ----
    // A x4: matrices {m0-7/k0-7, m8-15/k0-7, m0-7/k8-15, m8-15/k8-15}
    const int a_m  = wm * 32 + (lid & 7) + ((lid >> 3) & 1) * 8;  // + mi*16
    const int a_kq = (lid >> 4) & 1;                               // 8k-chunk half
    // B x4: matrices {n0-7/k0-7, n0-7/k8-15, n8-15/k0-7, n8-15/k8-15}
    const int b_n  = wn * 64 + (lid & 7) + ((lid >> 4) & 1) * 8;  // + q*16
    const int b_kq = (lid >> 3) & 1;

    // ---- staging helper: chunk c into ring slot s ----
    auto stage = [&](int c, int s) {
        const int kind = (c >= KTAPS) ? 1 : 0;
        const int t    = c - kind * KTAPS;
        // A: pre-swizzled 16 KB tile, linear copy (1024 x 16B)
        const char* srcA = (const char*)g_Ah + (size_t)((b * 2 + kind) * KTAPS + t) * A_BYTES;
        const uint32_t dA = sb + s * STAGE;
        #pragma unroll
        for (int it = 0; it < 2; ++it) {
            const int i = tid + it * 512;          // 0..1023
            cp_async16(dA + i * 16, srcA + i * 16);
        }
        // B: im2col gather, 2048 x 16B (8 channels each)
        const __half* srcT = kind ? g_dxTh : g_xTh;
        const int dz  = t / 9;
        const int dyy = (t % 9) / 3;
        const int dxx = t % 3;
        const int rb  = ((b * 64 + (z0 + dz)) * 64 + (y0 + dyy)) * 64 + dxx;
        const uint32_t dB = sb + s * STAGE + A_BYTES;
        #pragma unroll
        for (int it = 0; it < 4; ++it) {
            const int i  = tid + it * 512;         // 0..2047
            const int n  = i >> 3;
            const int c8 = i & 7;
            const int rr = rb + (n >> 6) * 64 + (n & 63);
            cp_async16(dB + n * 128 + ((c8 ^ (n & 7)) << 4),
                       (const char*)srcT + (size_t)rr * 128 + c8 * 16);
        }
    };

    // ---- prologue: fill 3 of 4 stages ----
    stage(0, 0); asm volatile("cp.async.commit_group;" ::: "memory");
    stage(1, 1); asm volatile("cp.async.commit_group;" ::: "memory");
    stage(2, 2); asm volatile("cp.async.commit_group;" ::: "memory");

    for (int c = 0; c < NCHUNK; ++c) {
        // my copies for chunk c done (c+1, c+2 remain pending)
        asm volatile("cp.async.wait_group %0;" :: "n"(NSTAGE - 2) : "memory");
        // all threads' copies visible; all warps finished compute(c-1)
        __syncthreads();
        if (c + 3 < NCHUNK) stage(c + 3, (c + 3) & 3);
        asm volatile("cp.async.commit_group;" ::: "memory");

        const int s = c & 3;
        const bool active = !(c >= KTAPS && wm < 2);
        if (active) {
            const uint32_t As = sb + s * STAGE;
            const uint32_t Bs = As + A_BYTES;
            #pragma unroll
            for (int ks = 0; ks < 4; ++ks) {          // K = 4 x 16
                const int kq_a = ks * 2 + a_kq;       // 8k-chunk index 0..7
                const int kq_b = ks * 2 + b_kq;
                uint32_t a[2][4];
                #pragma unroll
                for (int mi = 0; mi < 2; ++mi) {
                    const int m = a_m + mi * 16;
                    LDMATRIX_X4(a[mi][0], a[mi][1], a[mi][2], a[mi][3],
                                As + m * 128 + ((kq_a ^ (m & 7)) << 4));
                }
                uint32_t bq[4][4];
                #pragma unroll
                for (int q = 0; q < 4; ++q) {
                    const int n = b_n + q * 16;
                    LDMATRIX_X4(bq[q][0], bq[q][1], bq[q][2], bq[q][3],
                                Bs + n * 128 + ((kq_b ^ (n & 7)) << 4));
                }
                #pragma unroll
                for (int mi = 0; mi < 2; ++mi)
                    #pragma unroll
                    for (int q = 0; q < 4; ++q) {
                        mma_f16(acc[mi][2 * q + 0], a[mi], &bq[q][0]);
                        mma_f16(acc[mi][2 * q + 1], a[mi], &bq[q][2]);
                    }
            }
        }
    }

    // ---- epilogue ----
    const size_t NOUT   = (size_t)DOUT * DOUT * DOUT;
    const size_t dy_off = (size_t)B_ * COUT * NOUT;
    const int m_base = wm * 32;
    const int n_base = wn * 64;

    #pragma unroll
    for (int mi = 0; mi < 2; ++mi) {
        #pragma unroll
        for (int h = 0; h < 2; ++h) {
            const int m  = m_base + mi * 16 + h * 8 + g;
            const bool isy = (m < 64);
            const int co = m & 63;
            const float bv = isy ? bias[co] : 0.f;
            const size_t outadd = isy ? 0 : dy_off;
            const size_t ob = ((size_t)(b * COUT + co) * DOUT + z0) * DOUT;
            #pragma unroll
            for (int ni = 0; ni < 8; ++ni) {
                const int n  = n_base + ni * 8 + ct * 2;
                const int yo = y0 + (n >> 6);
                const int xo = n & 63;
                if (yo < DOUT) {
                    const size_t idx = (ob + yo) * DOUT + xo;
                    if (xo < DOUT) {
                        out[outadd + idx]     = acc[mi][ni][h * 2 + 0] + bv;
                        out[outadd + idx + 1] = acc[mi][ni][h * 2 + 1] + bv;  // xo even => xo+1 valid
                    }
                }
            }
        }
    }
}

// ---------------------------------------------------------------------------
// Launch. Inputs: x, s, dx, style_weight, style_bias, weight, bias.
// Output: concat(y, dy) fp32.
// ---------------------------------------------------------------------------
extern "C" void kernel_launch(void* const* d_in, const int* in_sizes, int n_in,
                              void* d_out, int out_size)
{
    const float* x    = (const float*)d_in[0];
    const float* s    = (const float*)d_in[1];
    const float* dx   = (const float*)d_in[2];
    const float* sw   = (const float*)d_in[3];
    const float* sb   = (const float*)d_in[4];
    const float* w    = (const float*)d_in[5];
    const float* bias = (const float*)d_in[6];
    float* out = (float*)d_out;

    cudaFuncSetAttribute(conv_mma_kernel, cudaFuncAttributeMaxDynamicSharedMemorySize, SMEM_DYN);

    prep_kernel<<<B_ * COUT, 256>>>(s, sw, sb, w);
    pack_kernel<<<B_ * 2 * KTAPS, 256>>>();
    transpose_kernel<<<dim3(64, 64, B_), dim3(32, 8)>>>(x, dx);
    conv_mma_kernel<<<dim3(16, 62, B_), 512, SMEM_DYN>>>(bias, out);
}

// round 10
// speedup vs baseline: 2.1966x; 1.0326x over previous
#include <cuda_runtime.h>
#include <cuda_fp16.h>
#include <cstdint>
#include <math.h>

// ---------------- problem constants ----------------
#define B_    2
#define CIN   64
#define COUT  64
#define DIN   64
#define DOUT  62
#define KTAPS 27
#define EPS_  1e-8f

#define NCHUNK 54                  // 27 taps x {x, dx}, K=64 each
#define A_BYTES 16384              // 128 m x 64 k fp16
#define B_BYTES 32768              // 256 n x 64 k fp16
#define STAGE   (A_BYTES + B_BYTES)   // 49152
#define NSTAGE  4
#define SMEM_DYN (NSTAGE * STAGE)     // 196608

// ---------------- device scratch ----------------
__device__ float g_wnv[B_ * COUT * CIN * KTAPS];
__device__ float g_dwv[B_ * COUT * CIN * KTAPS];
// A tiles fp16, pre-swizzled [b][kind][tap] x (128 m x 64 k), row=128B,
// 16B-chunk c stored at c ^ (m&7)
__device__ __align__(16) __half g_Ah[B_ * 2 * KTAPS * 128 * 64];
// channel-last fp16 inputs [b][z][y][x][c] (row = 64 ch = 128B), + overread pad
__device__ __align__(16) __half g_xTh [B_ * DIN * DIN * DIN * CIN + 32768];
__device__ __align__(16) __half g_dxTh[B_ * DIN * DIN * DIN * CIN + 32768];

// ---------------- helpers ----------------
__device__ __forceinline__ uint32_t smem_u32(const void* p) {
    uint32_t a;
    asm("{ .reg .u64 t; cvta.to.shared.u64 t, %1; cvt.u32.u64 %0, t; }" : "=r"(a) : "l"(p));
    return a;
}
__device__ __forceinline__ void cp_async16(uint32_t dst, const void* src) {
    asm volatile("cp.async.cg.shared.global [%0], [%1], 16;" :: "r"(dst), "l"(src) : "memory");
}
#define LDMATRIX_X4(r0, r1, r2, r3, addr) \
    asm volatile("ldmatrix.sync.aligned.m8n8.x4.shared.b16 {%0,%1,%2,%3}, [%4];" \
        : "=r"(r0), "=r"(r1), "=r"(r2), "=r"(r3) : "r"(addr))

__device__ __forceinline__ void mma_f16(float* d, const uint32_t* a, const uint32_t* b2) {
    asm volatile(
        "mma.sync.aligned.m16n8k16.row.col.f32.f16.f16.f32 "
        "{%0,%1,%2,%3}, {%4,%5,%6,%7}, {%8,%9}, {%0,%1,%2,%3};"
        : "+f"(d[0]), "+f"(d[1]), "+f"(d[2]), "+f"(d[3])
        : "r"(a[0]), "r"(a[1]), "r"(a[2]), "r"(a[3]), "r"(b2[0]), "r"(b2[1]));
}

// ---------------------------------------------------------------------------
// Prep: style modulation + demodulation (validated round 2)
// ---------------------------------------------------------------------------
__global__ void prep_kernel(const float* __restrict__ s,
                            const float* __restrict__ style_weight,
                            const float* __restrict__ style_bias,
                            const float* __restrict__ weight)
{
    __shared__ float wsm[CIN * KTAPS];
    __shared__ float dwsm[CIN * KTAPS];
    __shared__ float red0[256];
    __shared__ float red1[256];

    const int b  = blockIdx.x >> 6;
    const int co = blockIdx.x & 63;
    const int tid = threadIdx.x;

    const float s0 = s[b * 2 + 0];
    const float s1 = s[b * 2 + 1];

    float sw2 = 0.f, swd = 0.f;
    for (int e = tid; e < CIN * KTAPS; e += 256) {
        const int ci = e / KTAPS;
        const float smod  = s0 * style_weight[ci * 2 + 0]
                          + s1 * style_weight[ci * 2 + 1]
                          + style_bias[ci];
        const float dsmod = style_weight[ci * 2 + 1];
        const float wt = weight[(co * CIN) * KTAPS + e];
        const float wv = wt * smod;
        const float dv = wt * dsmod;
        wsm[e]  = wv;
        dwsm[e] = dv;
        sw2 += wv * wv;
        swd += wv * dv;
    }
    red0[tid] = sw2;
    red1[tid] = swd;
    __syncthreads();
    for (int st = 128; st > 0; st >>= 1) {
        if (tid < st) { red0[tid] += red0[tid + st]; red1[tid] += red1[tid + st]; }
        __syncthreads();
    }
    const float norm  = sqrtf(red0[0] + EPS_);
    const float inv   = 1.0f / norm;
    const float dnorm = -red1[0] * inv * inv * inv;

    const size_t ob = (size_t)(b * COUT + co) * (CIN * KTAPS);
    for (int e = tid; e < CIN * KTAPS; e += 256) {
        g_wnv[ob + e] = wsm[e] * inv;
        g_dwv[ob + e] = dwsm[e] * inv + wsm[e] * dnorm;
    }
}

// ---------------------------------------------------------------------------
// Pack A tiles: fp16, [m=128][k=64] rows of 128B; 16B chunk (k>>3) stored at
// (k>>3) ^ (m&7)  ->  ldmatrix conflict-free.
//   kind 0 (B = x):  m<64 -> wn[co=m],  m>=64 -> dw[co=m-64]
//   kind 1 (B = dx): m<64 -> 0,         m>=64 -> wn[co=m-64]
// ---------------------------------------------------------------------------
__global__ void pack_kernel()
{
    const int blk  = blockIdx.x;
    const int t    = blk % KTAPS;
    const int kind = (blk / KTAPS) & 1;
    const int b    = blk / (2 * KTAPS);
    char* dst = (char*)g_Ah + (size_t)blk * A_BYTES;

    for (int e = threadIdx.x; e < 128 * 64; e += 256) {
        const int m = e >> 6;
        const int k = e & 63;
        float v = 0.f;
        if (kind == 0) {
            v = (m < 64)
              ? g_wnv[(size_t)(b * COUT + m)        * (CIN * KTAPS) + k * KTAPS + t]
              : g_dwv[(size_t)(b * COUT + (m - 64)) * (CIN * KTAPS) + k * KTAPS + t];
        } else if (m >= 64) {
            v = g_wnv[(size_t)(b * COUT + (m - 64)) * (CIN * KTAPS) + k * KTAPS + t];
        }
        const uint32_t off = (uint32_t)(m * 128 + (((k >> 3) ^ (m & 7)) << 4) + (k & 7) * 2);
        *(__half*)(dst + off) = __float2half_rn(v);
    }
}

// ---------------------------------------------------------------------------
// Transpose NCDHW -> fp16 channel-last [b][z][y][x][c].
// ---------------------------------------------------------------------------
__global__ void transpose_kernel(const float* __restrict__ x, const float* __restrict__ dx)
{
    __shared__ float tile[64][65];
    const int tx = threadIdx.x;            // 0..31
    const int ty = threadIdx.y;            // 0..7
    const int y = blockIdx.x, z = blockIdx.y, b = blockIdx.z;

    const size_t in_base = (size_t)(b * 64) * 262144 + (size_t)z * 4096 + (size_t)y * 64;
    const size_t r0 = (((size_t)(b * 64 + z)) * 64 + y) * 64;

    const float* srcs[2] = { x, dx };
    __half* dsts[2] = { g_xTh, g_dxTh };

    for (int pass = 0; pass < 2; pass++) {
        const float* src = srcs[pass];
        __half* dst = dsts[pass];
        __syncthreads();
        for (int c = ty; c < 64; c += 8) {
            tile[c][tx]      = src[in_base + (size_t)c * 262144 + tx];
            tile[c][tx + 32] = src[in_base + (size_t)c * 262144 + tx + 32];
        }
        __syncthreads();
        for (int xr = ty; xr < 64; xr += 8) {
            dst[(r0 + xr) * 64 + tx]      = __float2half_rn(tile[tx][xr]);
            dst[(r0 + xr) * 64 + tx + 32] = __float2half_rn(tile[tx + 32][xr]);
        }
    }
}

// ---------------------------------------------------------------------------
// Conv implicit-GEMM, fp16 mma.sync m16n8k16 + ldmatrix.
// Grid (16 ytiles, 62 z, 2 b); 512 threads = 16 warps (4M x 4N), warp m32xn64.
// 54 chunks of K=64; 4-stage cp.async ring, one barrier per chunk.
// All staging addresses hoisted out of the chunk loop; dx-chunks copy only the
// meaningful A half (rows 64..127); loop split x-chunks / dx-chunks.
// ---------------------------------------------------------------------------
__global__ __launch_bounds__(512, 1) void conv_mma_kernel(
    const float* __restrict__ bias, float* __restrict__ out)
{
    extern __shared__ __align__(16) char smem[];
    const uint32_t sb = smem_u32(smem);

    const int tid = threadIdx.x;
    const int wid = tid >> 5;
    const int lid = tid & 31;
    const int wm  = wid >> 2;          // M tile 0..3 (rows wm*32..)
    const int wn  = wid & 3;           // N tile 0..3 (cols wn*64..)
    const int g   = lid >> 2;          // 0..7
    const int ct  = lid & 3;           // 0..3

    const int y0 = blockIdx.x * 4;
    const int z0 = blockIdx.y;
    const int b  = blockIdx.z;

    float acc[2][8][4];
    #pragma unroll
    for (int mi = 0; mi < 2; ++mi)
        #pragma unroll
        for (int ni = 0; ni < 8; ++ni)
            #pragma unroll
            for (int j = 0; j < 4; ++j) acc[mi][ni][j] = 0.f;

    // ---- per-thread ldmatrix row indices ----
    const int a_m  = wm * 32 + (lid & 7) + ((lid >> 3) & 1) * 8;  // + mi*16
    const int a_kq = (lid >> 4) & 1;
    const int b_n  = wn * 64 + (lid & 7) + ((lid >> 4) & 1) * 8;  // + q*16
    const int b_kq = (lid >> 3) & 1;

    // ---- hoisted staging offsets (chunk-invariant) ----
    const uint32_t aOff0 = (uint32_t)tid * 16;            // A rows 0..63
    const uint32_t aOff1 = (uint32_t)(tid + 512) * 16;    // A rows 64..127
    uint32_t bDst[4];
    uint32_t bSrc[4];
    #pragma unroll
    for (int it = 0; it < 4; ++it) {
        const int i  = tid + it * 512;
        const int n  = i >> 3;
        const int c8 = i & 7;
        bDst[it] = (uint32_t)(A_BYTES + n * 128 + ((c8 ^ (n & 7)) << 4));
        bSrc[it] = (uint32_t)((((n >> 6) * 64 + (n & 63)) * 128) + c8 * 16);
    }
    // chunk-invariant source bases
    const int rb0 = ((b * 64 + z0) * 64 + y0) * 64;
    const char* xB  = (const char*)g_xTh  + (size_t)rb0 * 128;
    const char* dxB = (const char*)g_dxTh + (size_t)rb0 * 128;
    const char* aBaseX  = (const char*)g_Ah + (size_t)(b * 2)     * KTAPS * A_BYTES;
    const char* aBaseDX = (const char*)g_Ah + (size_t)(b * 2 + 1) * KTAPS * A_BYTES;

    // ---- staging: chunk c into ring slot s ----
    auto stage = [&](int c, int s) {
        const int kind = (c >= KTAPS) ? 1 : 0;
        const int t    = c - (kind ? KTAPS : 0);
        const int dz   = t / 9;
        const int r1   = t - dz * 9;
        const int dyy  = r1 / 3;
        const int dxx  = r1 - dyy * 3;
        const uint32_t d = sb + s * STAGE;
        // A tile (pre-swizzled, linear copy); dx-chunks: rows 0..63 unused
        const char* srcA = (kind ? aBaseDX : aBaseX) + (size_t)t * A_BYTES;
        if (!kind) cp_async16(d + aOff0, srcA + aOff0);
        cp_async16(d + aOff1, srcA + aOff1);
        // B tile: im2col gather with hoisted offsets
        const char* srcB = (kind ? dxB : xB) + (size_t)(dz * 4096 + dyy * 64 + dxx) * 128;
        #pragma unroll
        for (int it = 0; it < 4; ++it)
            cp_async16(d + bDst[it], srcB + bSrc[it]);
    };

    // ---- compute one chunk from ring slot s ----
    auto compute = [&](int s) {
        const uint32_t As = sb + s * STAGE;
        const uint32_t Bs = As + A_BYTES;
        #pragma unroll
        for (int ks = 0; ks < 4; ++ks) {
            const int kq_a = ks * 2 + a_kq;
            const int kq_b = ks * 2 + b_kq;
            uint32_t a[2][4];
            #pragma unroll
            for (int mi = 0; mi < 2; ++mi) {
                const int m = a_m + mi * 16;
                LDMATRIX_X4(a[mi][0], a[mi][1], a[mi][2], a[mi][3],
                            As + m * 128 + ((kq_a ^ (m & 7)) << 4));
            }
            uint32_t bq[4][4];
            #pragma unroll
            for (int q = 0; q < 4; ++q) {
                const int n = b_n + q * 16;
                LDMATRIX_X4(bq[q][0], bq[q][1], bq[q][2], bq[q][3],
                            Bs + n * 128 + ((kq_b ^ (n & 7)) << 4));
            }
            #pragma unroll
            for (int mi = 0; mi < 2; ++mi)
                #pragma unroll
                for (int q = 0; q < 4; ++q) {
                    mma_f16(acc[mi][2 * q + 0], a[mi], &bq[q][0]);
                    mma_f16(acc[mi][2 * q + 1], a[mi], &bq[q][2]);
                }
        }
    };

    // ---- prologue: fill 3 of 4 stages ----
    stage(0, 0); asm volatile("cp.async.commit_group;" ::: "memory");
    stage(1, 1); asm volatile("cp.async.commit_group;" ::: "memory");
    stage(2, 2); asm volatile("cp.async.commit_group;" ::: "memory");

    // ---- x-chunks: all 16 warps compute ----
    for (int c = 0; c < KTAPS; ++c) {
        asm volatile("cp.async.wait_group %0;" :: "n"(NSTAGE - 2) : "memory");
        __syncthreads();
        stage(c + 3, (c + 3) & 3);   // c+3 <= 29 < 54, always valid
        asm volatile("cp.async.commit_group;" ::: "memory");
        compute(c & 3);
    }
    // ---- dx-chunks: wm<2 warps only stage/sync ----
    for (int c = KTAPS; c < NCHUNK; ++c) {
        asm volatile("cp.async.wait_group %0;" :: "n"(NSTAGE - 2) : "memory");
        __syncthreads();
        if (c + 3 < NCHUNK) stage(c + 3, (c + 3) & 3);
        asm volatile("cp.async.commit_group;" ::: "memory");
        if (wm >= 2) compute(c & 3);
    }

    // ---- epilogue ----
    const size_t NOUT   = (size_t)DOUT * DOUT * DOUT;
    const size_t dy_off = (size_t)B_ * COUT * NOUT;
    const int m_base = wm * 32;
    const int n_base = wn * 64;

    #pragma unroll
    for (int mi = 0; mi < 2; ++mi) {
        #pragma unroll
        for (int h = 0; h < 2; ++h) {
            const int m  = m_base + mi * 16 + h * 8 + g;
            const bool isy = (m < 64);
            const int co = m & 63;
            const float bv = isy ? bias[co] : 0.f;
            const size_t outadd = isy ? 0 : dy_off;
            const size_t ob = ((size_t)(b * COUT + co) * DOUT + z0) * DOUT;
            #pragma unroll
            for (int ni = 0; ni < 8; ++ni) {
                const int n  = n_base + ni * 8 + ct * 2;
                const int yo = y0 + (n >> 6);
                const int xo = n & 63;
                if (yo < DOUT) {
                    const size_t idx = (ob + yo) * DOUT + xo;
                    if (xo < DOUT) {
                        out[outadd + idx]     = acc[mi][ni][h * 2 + 0] + bv;
                        out[outadd + idx + 1] = acc[mi][ni][h * 2 + 1] + bv;  // xo even => xo+1 valid
                    }
                }
            }
        }
    }
}

// ---------------------------------------------------------------------------
// Launch. Inputs: x, s, dx, style_weight, style_bias, weight, bias.
// Output: concat(y, dy) fp32.
// ---------------------------------------------------------------------------
extern "C" void kernel_launch(void* const* d_in, const int* in_sizes, int n_in,
                              void* d_out, int out_size)
{
    const float* x    = (const float*)d_in[0];
    const float* s    = (const float*)d_in[1];
    const float* dx   = (const float*)d_in[2];
    const float* sw   = (const float*)d_in[3];
    const float* sb   = (const float*)d_in[4];
    const float* w    = (const float*)d_in[5];
    const float* bias = (const float*)d_in[6];
    float* out = (float*)d_out;

    cudaFuncSetAttribute(conv_mma_kernel, cudaFuncAttributeMaxDynamicSharedMemorySize, SMEM_DYN);

    prep_kernel<<<B_ * COUT, 256>>>(s, sw, sb, w);
    pack_kernel<<<B_ * 2 * KTAPS, 256>>>();
    transpose_kernel<<<dim3(64, 64, B_), dim3(32, 8)>>>(x, dx);
    conv_mma_kernel<<<dim3(16, 62, B_), 512, SMEM_DYN>>>(bias, out);
}

// round 11
// speedup vs baseline: 2.2351x; 1.0175x over previous
#include <cuda_runtime.h>
#include <cuda_fp16.h>
#include <cstdint>
#include <math.h>

// ---------------- problem constants ----------------
#define B_    2
#define CIN   64
#define COUT  64
#define DIN   64
#define DOUT  62
#define KTAPS 27
#define EPS_  1e-8f

#define NCHUNK 54                  // 27 taps x {x, dx}, K=64 each
#define A_BYTES 16384              // 128 m x 64 k fp16
#define B_BYTES 32768              // 256 n x 64 k fp16
#define STAGE   (A_BYTES + B_BYTES)   // 49152
#define NSTAGE  4
#define SMEM_DYN (NSTAGE * STAGE)     // 196608

// ---------------- device scratch ----------------
__device__ float g_wnv[B_ * COUT * CIN * KTAPS];
__device__ float g_dwv[B_ * COUT * CIN * KTAPS];
// A tiles fp16, pre-swizzled [b][kind][tap] x (128 m x 64 k), row=128B,
// 16B-chunk c stored at c ^ (m&7)
__device__ __align__(16) __half g_Ah[B_ * 2 * KTAPS * 128 * 64];
// channel-last fp16 inputs [b][z][y][x][c] (row = 64 ch = 128B), + overread pad
__device__ __align__(16) __half g_xTh [B_ * DIN * DIN * DIN * CIN + 32768];
__device__ __align__(16) __half g_dxTh[B_ * DIN * DIN * DIN * CIN + 32768];

// ---------------- helpers ----------------
__device__ __forceinline__ uint32_t smem_u32(const void* p) {
    uint32_t a;
    asm("{ .reg .u64 t; cvta.to.shared.u64 t, %1; cvt.u32.u64 %0, t; }" : "=r"(a) : "l"(p));
    return a;
}
__device__ __forceinline__ void cp_async16(uint32_t dst, const void* src) {
    asm volatile("cp.async.cg.shared.global [%0], [%1], 16;" :: "r"(dst), "l"(src) : "memory");
}
#define LDMATRIX_X4(r0, r1, r2, r3, addr) \
    asm volatile("ldmatrix.sync.aligned.m8n8.x4.shared.b16 {%0,%1,%2,%3}, [%4];" \
        : "=r"(r0), "=r"(r1), "=r"(r2), "=r"(r3) : "r"(addr))

__device__ __forceinline__ void mma_f16(float* d, const uint32_t* a, const uint32_t* b2) {
    asm volatile(
        "mma.sync.aligned.m16n8k16.row.col.f32.f16.f16.f32 "
        "{%0,%1,%2,%3}, {%4,%5,%6,%7}, {%8,%9}, {%0,%1,%2,%3};"
        : "+f"(d[0]), "+f"(d[1]), "+f"(d[2]), "+f"(d[3])
        : "r"(a[0]), "r"(a[1]), "r"(a[2]), "r"(a[3]), "r"(b2[0]), "r"(b2[1]));
}

// ---------------------------------------------------------------------------
// Prep: style modulation + demodulation (validated round 2)
// ---------------------------------------------------------------------------
__global__ void prep_kernel(const float* __restrict__ s,
                            const float* __restrict__ style_weight,
                            const float* __restrict__ style_bias,
                            const float* __restrict__ weight)
{
    __shared__ float wsm[CIN * KTAPS];
    __shared__ float dwsm[CIN * KTAPS];
    __shared__ float red0[256];
    __shared__ float red1[256];

    const int b  = blockIdx.x >> 6;
    const int co = blockIdx.x & 63;
    const int tid = threadIdx.x;

    const float s0 = s[b * 2 + 0];
    const float s1 = s[b * 2 + 1];

    float sw2 = 0.f, swd = 0.f;
    for (int e = tid; e < CIN * KTAPS; e += 256) {
        const int ci = e / KTAPS;
        const float smod  = s0 * style_weight[ci * 2 + 0]
                          + s1 * style_weight[ci * 2 + 1]
                          + style_bias[ci];
        const float dsmod = style_weight[ci * 2 + 1];
        const float wt = weight[(co * CIN) * KTAPS + e];
        const float wv = wt * smod;
        const float dv = wt * dsmod;
        wsm[e]  = wv;
        dwsm[e] = dv;
        sw2 += wv * wv;
        swd += wv * dv;
    }
    red0[tid] = sw2;
    red1[tid] = swd;
    __syncthreads();
    for (int st = 128; st > 0; st >>= 1) {
        if (tid < st) { red0[tid] += red0[tid + st]; red1[tid] += red1[tid + st]; }
        __syncthreads();
    }
    const float norm  = sqrtf(red0[0] + EPS_);
    const float inv   = 1.0f / norm;
    const float dnorm = -red1[0] * inv * inv * inv;

    const size_t ob = (size_t)(b * COUT + co) * (CIN * KTAPS);
    for (int e = tid; e < CIN * KTAPS; e += 256) {
        g_wnv[ob + e] = wsm[e] * inv;
        g_dwv[ob + e] = dwsm[e] * inv + wsm[e] * dnorm;
    }
}

// ---------------------------------------------------------------------------
// Pack A tiles: fp16, [m=128][k=64] rows of 128B; 16B chunk (k>>3) stored at
// (k>>3) ^ (m&7)  ->  ldmatrix conflict-free.
//   kind 0 (B = x):  m<64 -> wn[co=m],  m>=64 -> dw[co=m-64]
//   kind 1 (B = dx): m<64 -> 0,         m>=64 -> wn[co=m-64]
// ---------------------------------------------------------------------------
__global__ void pack_kernel()
{
    const int blk  = blockIdx.x;
    const int t    = blk % KTAPS;
    const int kind = (blk / KTAPS) & 1;
    const int b    = blk / (2 * KTAPS);
    char* dst = (char*)g_Ah + (size_t)blk * A_BYTES;

    for (int e = threadIdx.x; e < 128 * 64; e += 256) {
        const int m = e >> 6;
        const int k = e & 63;
        float v = 0.f;
        if (kind == 0) {
            v = (m < 64)
              ? g_wnv[(size_t)(b * COUT + m)        * (CIN * KTAPS) + k * KTAPS + t]
              : g_dwv[(size_t)(b * COUT + (m - 64)) * (CIN * KTAPS) + k * KTAPS + t];
        } else if (m >= 64) {
            v = g_wnv[(size_t)(b * COUT + (m - 64)) * (CIN * KTAPS) + k * KTAPS + t];
        }
        const uint32_t off = (uint32_t)(m * 128 + (((k >> 3) ^ (m & 7)) << 4) + (k & 7) * 2);
        *(__half*)(dst + off) = __float2half_rn(v);
    }
}

// ---------------------------------------------------------------------------
// Transpose NCDHW -> fp16 channel-last [b][z][y][x][c].
// ---------------------------------------------------------------------------
__global__ void transpose_kernel(const float* __restrict__ x, const float* __restrict__ dx)
{
    __shared__ float tile[64][65];
    const int tx = threadIdx.x;            // 0..31
    const int ty = threadIdx.y;            // 0..7
    const int y = blockIdx.x, z = blockIdx.y, b = blockIdx.z;

    const size_t in_base = (size_t)(b * 64) * 262144 + (size_t)z * 4096 + (size_t)y * 64;
    const size_t r0 = (((size_t)(b * 64 + z)) * 64 + y) * 64;

    const float* srcs[2] = { x, dx };
    __half* dsts[2] = { g_xTh, g_dxTh };

    for (int pass = 0; pass < 2; pass++) {
        const float* src = srcs[pass];
        __half* dst = dsts[pass];
        __syncthreads();
        for (int c = ty; c < 64; c += 8) {
            tile[c][tx]      = src[in_base + (size_t)c * 262144 + tx];
            tile[c][tx + 32] = src[in_base + (size_t)c * 262144 + tx + 32];
        }
        __syncthreads();
        for (int xr = ty; xr < 64; xr += 8) {
            dst[(r0 + xr) * 64 + tx]      = __float2half_rn(tile[tx][xr]);
            dst[(r0 + xr) * 64 + tx + 32] = __float2half_rn(tile[tx + 32][xr]);
        }
    }
}

// ---------------------------------------------------------------------------
// Conv implicit-GEMM, fp16 mma.sync m16n8k16 + ldmatrix, explicit fragment
// double-buffering (ping-pong across ks) to overlap LDSM latency with HMMA.
// Grid (16 ytiles, 62 z, 2 b); 256 threads = 8 warps (2M x 4N), warp m64xn64.
// 54 chunks of K=64; 4-stage cp.async ring, one barrier per chunk.
// A smem: [m=128][k=64] fp16 rows 128B, chunk swizzle ^(m&7).
// B smem: [n=256][k=64] fp16 rows 128B, chunk swizzle ^(n&7).
// c < 27: B = x;  c >= 27: B = dx (A rows 0..63 zero -> wm==0 warps skip).
// ---------------------------------------------------------------------------
__global__ __launch_bounds__(256, 1) void conv_mma_kernel(
    const float* __restrict__ bias, float* __restrict__ out)
{
    extern __shared__ __align__(16) char smem[];
    const uint32_t sb = smem_u32(smem);

    const int tid = threadIdx.x;
    const int wid = tid >> 5;
    const int lid = tid & 31;
    const int wm  = wid >> 2;          // M tile 0..1 (rows wm*64..)
    const int wn  = wid & 3;           // N tile 0..3 (cols wn*64..)
    const int g   = lid >> 2;          // 0..7
    const int ct  = lid & 3;           // 0..3

    const int y0 = blockIdx.x * 4;
    const int z0 = blockIdx.y;
    const int b  = blockIdx.z;

    float acc[4][8][4];
    #pragma unroll
    for (int mi = 0; mi < 4; ++mi)
        #pragma unroll
        for (int ni = 0; ni < 8; ++ni)
            #pragma unroll
            for (int j = 0; j < 4; ++j) acc[mi][ni][j] = 0.f;

    // ---- per-thread ldmatrix row indices ----
    const int a_m  = wm * 64 + (lid & 7) + ((lid >> 3) & 1) * 8;  // + mi*16
    const int a_kq = (lid >> 4) & 1;
    const int b_n  = wn * 64 + (lid & 7) + ((lid >> 4) & 1) * 8;  // + q*16
    const int b_kq = (lid >> 3) & 1;

    // ---- hoisted staging offsets (chunk-invariant) ----
    uint32_t bDst[8];
    uint32_t bSrc[8];
    #pragma unroll
    for (int it = 0; it < 8; ++it) {
        const int i  = tid + it * 256;
        const int n  = i >> 3;
        const int c8 = i & 7;
        bDst[it] = (uint32_t)(A_BYTES + n * 128 + ((c8 ^ (n & 7)) << 4));
        bSrc[it] = (uint32_t)((((n >> 6) * 64 + (n & 63)) * 128) + c8 * 16);
    }
    const int rb0 = ((b * 64 + z0) * 64 + y0) * 64;
    const char* xB  = (const char*)g_xTh  + (size_t)rb0 * 128;
    const char* dxB = (const char*)g_dxTh + (size_t)rb0 * 128;
    const char* aBaseX  = (const char*)g_Ah + (size_t)(b * 2)     * KTAPS * A_BYTES;
    const char* aBaseDX = (const char*)g_Ah + (size_t)(b * 2 + 1) * KTAPS * A_BYTES;

    // ---- staging: chunk c into ring slot s ----
    auto stage = [&](int c, int s) {
        const int kind = (c >= KTAPS) ? 1 : 0;
        const int t    = c - (kind ? KTAPS : 0);
        const int dz   = t / 9;
        const int r1   = t - dz * 9;
        const int dyy  = r1 / 3;
        const int dxx  = r1 - dyy * 3;
        const uint32_t d = sb + s * STAGE;
        // A tile (pre-swizzled, linear copy); dx-chunks: rows 0..63 unused
        const char* srcA = (kind ? aBaseDX : aBaseX) + (size_t)t * A_BYTES;
        const uint32_t aOff = (uint32_t)tid * 16;
        if (!kind) {
            cp_async16(d + aOff,        srcA + aOff);
            cp_async16(d + aOff + 4096, srcA + aOff + 4096);
        }
        cp_async16(d + aOff + 8192,  srcA + aOff + 8192);
        cp_async16(d + aOff + 12288, srcA + aOff + 12288);
        // B tile: im2col gather with hoisted offsets
        const char* srcB = (kind ? dxB : xB) + (size_t)(dz * 4096 + dyy * 64 + dxx) * 128;
        #pragma unroll
        for (int it = 0; it < 8; ++it)
            cp_async16(d + bDst[it], srcB + bSrc[it]);
    };

    // ---- fragment load for one ks into given buffers ----
    auto load_frags = [&](int ks, uint32_t As, uint32_t Bs,
                          uint32_t (*a)[4], uint32_t (*bq)[4]) {
        const int kq_a = ks * 2 + a_kq;
        const int kq_b = ks * 2 + b_kq;
        #pragma unroll
        for (int mi = 0; mi < 4; ++mi) {
            const int m = a_m + mi * 16;
            LDMATRIX_X4(a[mi][0], a[mi][1], a[mi][2], a[mi][3],
                        As + m * 128 + ((kq_a ^ (m & 7)) << 4));
        }
        #pragma unroll
        for (int q = 0; q < 4; ++q) {
            const int n = b_n + q * 16;
            LDMATRIX_X4(bq[q][0], bq[q][1], bq[q][2], bq[q][3],
                        Bs + n * 128 + ((kq_b ^ (n & 7)) << 4));
        }
    };

    // ---- compute one chunk from ring slot s (ping-pong over ks) ----
    auto compute = [&](int s) {
        const uint32_t As = sb + s * STAGE;
        const uint32_t Bs = As + A_BYTES;
        uint32_t af[2][4][4];
        uint32_t bf[2][4][4];
        load_frags(0, As, Bs, af[0], bf[0]);
        #pragma unroll
        for (int ks = 0; ks < 4; ++ks) {
            const int cur = ks & 1;
            if (ks < 3) load_frags(ks + 1, As, Bs, af[cur ^ 1], bf[cur ^ 1]);
            #pragma unroll
            for (int mi = 0; mi < 4; ++mi)
                #pragma unroll
                for (int q = 0; q < 4; ++q) {
                    mma_f16(acc[mi][2 * q + 0], af[cur][mi], &bf[cur][q][0]);
                    mma_f16(acc[mi][2 * q + 1], af[cur][mi], &bf[cur][q][2]);
                }
        }
    };

    // ---- prologue: fill 3 of 4 stages ----
    stage(0, 0); asm volatile("cp.async.commit_group;" ::: "memory");
    stage(1, 1); asm volatile("cp.async.commit_group;" ::: "memory");
    stage(2, 2); asm volatile("cp.async.commit_group;" ::: "memory");

    // ---- x-chunks: all 8 warps compute ----
    for (int c = 0; c < KTAPS; ++c) {
        asm volatile("cp.async.wait_group %0;" :: "n"(NSTAGE - 2) : "memory");
        __syncthreads();
        stage(c + 3, (c + 3) & 3);   // c+3 <= 29 < 54, always valid
        asm volatile("cp.async.commit_group;" ::: "memory");
        compute(c & 3);
    }
    // ---- dx-chunks: wm==0 warps only stage/sync ----
    for (int c = KTAPS; c < NCHUNK; ++c) {
        asm volatile("cp.async.wait_group %0;" :: "n"(NSTAGE - 2) : "memory");
        __syncthreads();
        if (c + 3 < NCHUNK) stage(c + 3, (c + 3) & 3);
        asm volatile("cp.async.commit_group;" ::: "memory");
        if (wm == 1) compute(c & 3);
    }

    // ---- epilogue ----
    const size_t NOUT   = (size_t)DOUT * DOUT * DOUT;
    const size_t dy_off = (size_t)B_ * COUT * NOUT;
    const int m_base = wm * 64;
    const int n_base = wn * 64;

    #pragma unroll
    for (int mi = 0; mi < 4; ++mi) {
        #pragma unroll
        for (int h = 0; h < 2; ++h) {
            const int m  = m_base + mi * 16 + h * 8 + g;
            const bool isy = (m < 64);
            const int co = m & 63;
            const float bv = isy ? bias[co] : 0.f;
            const size_t outadd = isy ? 0 : dy_off;
            const size_t ob = ((size_t)(b * COUT + co) * DOUT + z0) * DOUT;
            #pragma unroll
            for (int ni = 0; ni < 8; ++ni) {
                const int n  = n_base + ni * 8 + ct * 2;
                const int yo = y0 + (n >> 6);
                const int xo = n & 63;
                if (yo < DOUT) {
                    const size_t idx = (ob + yo) * DOUT + xo;
                    if (xo < DOUT) {
                        out[outadd + idx]     = acc[mi][ni][h * 2 + 0] + bv;
                        out[outadd + idx + 1] = acc[mi][ni][h * 2 + 1] + bv;  // xo even => xo+1 valid
                    }
                }
            }
        }
    }
}

// ---------------------------------------------------------------------------
// Launch. Inputs: x, s, dx, style_weight, style_bias, weight, bias.
// Output: concat(y, dy) fp32.
// ---------------------------------------------------------------------------
extern "C" void kernel_launch(void* const* d_in, const int* in_sizes, int n_in,
                              void* d_out, int out_size)
{
    const float* x    = (const float*)d_in[0];
    const float* s    = (const float*)d_in[1];
    const float* dx   = (const float*)d_in[2];
    const float* sw   = (const float*)d_in[3];
    const float* sb   = (const float*)d_in[4];
    const float* w    = (const float*)d_in[5];
    const float* bias = (const float*)d_in[6];
    float* out = (float*)d_out;

    cudaFuncSetAttribute(conv_mma_kernel, cudaFuncAttributeMaxDynamicSharedMemorySize, SMEM_DYN);

    prep_kernel<<<B_ * COUT, 256>>>(s, sw, sb, w);
    pack_kernel<<<B_ * 2 * KTAPS, 256>>>();
    transpose_kernel<<<dim3(64, 64, B_), dim3(32, 8)>>>(x, dx);
    conv_mma_kernel<<<dim3(16, 62, B_), 256, SMEM_DYN>>>(bias, out);
}

// round 12
// speedup vs baseline: 2.6711x; 1.1951x over previous
#include <cuda_runtime.h>
#include <cuda_fp16.h>
#include <cstdint>
#include <math.h>

// ---------------- problem constants ----------------
#define B_    2
#define CIN   64
#define COUT  64
#define DIN   64
#define DOUT  62
#define KTAPS 27
#define EPS_  1e-8f

#define NCHUNK 54                  // 27 taps x {x, dx}, K=64 each
#define A_BYTES 16384              // 128 m x 64 k fp16
#define B_BYTES 16384              // 128 n x 64 k fp16
#define STAGE   (A_BYTES + B_BYTES)   // 32768
#define NSTAGE  3
#define SMEM_DYN (NSTAGE * STAGE)     // 98304 per CTA -> 2 CTAs/SM

// ---------------- device scratch ----------------
__device__ float g_wnv[B_ * COUT * CIN * KTAPS];
__device__ float g_dwv[B_ * COUT * CIN * KTAPS];
// A tiles fp16, pre-swizzled [b][kind][tap] x (128 m x 64 k), row=128B,
// 16B-chunk c stored at c ^ (m&7)
__device__ __align__(16) __half g_Ah[B_ * 2 * KTAPS * 128 * 64];
// channel-last fp16 inputs [b][z][y][x][c] (row = 64 ch = 128B), + overread pad
__device__ __align__(16) __half g_xTh [B_ * DIN * DIN * DIN * CIN + 32768];
__device__ __align__(16) __half g_dxTh[B_ * DIN * DIN * DIN * CIN + 32768];

// ---------------- helpers ----------------
__device__ __forceinline__ uint32_t smem_u32(const void* p) {
    uint32_t a;
    asm("{ .reg .u64 t; cvta.to.shared.u64 t, %1; cvt.u32.u64 %0, t; }" : "=r"(a) : "l"(p));
    return a;
}
__device__ __forceinline__ void cp_async16(uint32_t dst, const void* src) {
    asm volatile("cp.async.cg.shared.global [%0], [%1], 16;" :: "r"(dst), "l"(src) : "memory");
}
#define LDMATRIX_X4(r0, r1, r2, r3, addr) \
    asm volatile("ldmatrix.sync.aligned.m8n8.x4.shared.b16 {%0,%1,%2,%3}, [%4];" \
        : "=r"(r0), "=r"(r1), "=r"(r2), "=r"(r3) : "r"(addr))

__device__ __forceinline__ void mma_f16(float* d, const uint32_t* a, const uint32_t* b2) {
    asm volatile(
        "mma.sync.aligned.m16n8k16.row.col.f32.f16.f16.f32 "
        "{%0,%1,%2,%3}, {%4,%5,%6,%7}, {%8,%9}, {%0,%1,%2,%3};"
        : "+f"(d[0]), "+f"(d[1]), "+f"(d[2]), "+f"(d[3])
        : "r"(a[0]), "r"(a[1]), "r"(a[2]), "r"(a[3]), "r"(b2[0]), "r"(b2[1]));
}

// ---------------------------------------------------------------------------
// Prep: style modulation + demodulation (validated round 2)
// ---------------------------------------------------------------------------
__global__ void prep_kernel(const float* __restrict__ s,
                            const float* __restrict__ style_weight,
                            const float* __restrict__ style_bias,
                            const float* __restrict__ weight)
{
    __shared__ float wsm[CIN * KTAPS];
    __shared__ float dwsm[CIN * KTAPS];
    __shared__ float red0[256];
    __shared__ float red1[256];

    const int b  = blockIdx.x >> 6;
    const int co = blockIdx.x & 63;
    const int tid = threadIdx.x;

    const float s0 = s[b * 2 + 0];
    const float s1 = s[b * 2 + 1];

    float sw2 = 0.f, swd = 0.f;
    for (int e = tid; e < CIN * KTAPS; e += 256) {
        const int ci = e / KTAPS;
        const float smod  = s0 * style_weight[ci * 2 + 0]
                          + s1 * style_weight[ci * 2 + 1]
                          + style_bias[ci];
        const float dsmod = style_weight[ci * 2 + 1];
        const float wt = weight[(co * CIN) * KTAPS + e];
        const float wv = wt * smod;
        const float dv = wt * dsmod;
        wsm[e]  = wv;
        dwsm[e] = dv;
        sw2 += wv * wv;
        swd += wv * dv;
    }
    red0[tid] = sw2;
    red1[tid] = swd;
    __syncthreads();
    for (int st = 128; st > 0; st >>= 1) {
        if (tid < st) { red0[tid] += red0[tid + st]; red1[tid] += red1[tid + st]; }
        __syncthreads();
    }
    const float norm  = sqrtf(red0[0] + EPS_);
    const float inv   = 1.0f / norm;
    const float dnorm = -red1[0] * inv * inv * inv;

    const size_t ob = (size_t)(b * COUT + co) * (CIN * KTAPS);
    for (int e = tid; e < CIN * KTAPS; e += 256) {
        g_wnv[ob + e] = wsm[e] * inv;
        g_dwv[ob + e] = dwsm[e] * inv + wsm[e] * dnorm;
    }
}

// ---------------------------------------------------------------------------
// Pack A tiles: fp16, [m=128][k=64] rows of 128B; 16B chunk (k>>3) stored at
// (k>>3) ^ (m&7)  ->  ldmatrix conflict-free.
//   kind 0 (B = x):  m<64 -> wn[co=m],  m>=64 -> dw[co=m-64]
//   kind 1 (B = dx): m<64 -> 0,         m>=64 -> wn[co=m-64]
// ---------------------------------------------------------------------------
__global__ void pack_kernel()
{
    const int blk  = blockIdx.x;
    const int t    = blk % KTAPS;
    const int kind = (blk / KTAPS) & 1;
    const int b    = blk / (2 * KTAPS);
    char* dst = (char*)g_Ah + (size_t)blk * A_BYTES;

    for (int e = threadIdx.x; e < 128 * 64; e += 256) {
        const int m = e >> 6;
        const int k = e & 63;
        float v = 0.f;
        if (kind == 0) {
            v = (m < 64)
              ? g_wnv[(size_t)(b * COUT + m)        * (CIN * KTAPS) + k * KTAPS + t]
              : g_dwv[(size_t)(b * COUT + (m - 64)) * (CIN * KTAPS) + k * KTAPS + t];
        } else if (m >= 64) {
            v = g_wnv[(size_t)(b * COUT + (m - 64)) * (CIN * KTAPS) + k * KTAPS + t];
        }
        const uint32_t off = (uint32_t)(m * 128 + (((k >> 3) ^ (m & 7)) << 4) + (k & 7) * 2);
        *(__half*)(dst + off) = __float2half_rn(v);
    }
}

// ---------------------------------------------------------------------------
// Transpose NCDHW -> fp16 channel-last [b][z][y][x][c].
// ---------------------------------------------------------------------------
__global__ void transpose_kernel(const float* __restrict__ x, const float* __restrict__ dx)
{
    __shared__ float tile[64][65];
    const int tx = threadIdx.x;            // 0..31
    const int ty = threadIdx.y;            // 0..7
    const int y = blockIdx.x, z = blockIdx.y, b = blockIdx.z;

    const size_t in_base = (size_t)(b * 64) * 262144 + (size_t)z * 4096 + (size_t)y * 64;
    const size_t r0 = (((size_t)(b * 64 + z)) * 64 + y) * 64;

    const float* srcs[2] = { x, dx };
    __half* dsts[2] = { g_xTh, g_dxTh };

    for (int pass = 0; pass < 2; pass++) {
        const float* src = srcs[pass];
        __half* dst = dsts[pass];
        __syncthreads();
        for (int c = ty; c < 64; c += 8) {
            tile[c][tx]      = src[in_base + (size_t)c * 262144 + tx];
            tile[c][tx + 32] = src[in_base + (size_t)c * 262144 + tx + 32];
        }
        __syncthreads();
        for (int xr = ty; xr < 64; xr += 8) {
            dst[(r0 + xr) * 64 + tx]      = __float2half_rn(tile[tx][xr]);
            dst[(r0 + xr) * 64 + tx + 32] = __float2half_rn(tile[tx + 32][xr]);
        }
    }
}

// ---------------------------------------------------------------------------
// Conv implicit-GEMM, fp16 mma.sync m16n8k16 + ldmatrix.
// CTA tile M=128 x N=128 (2 y-rows x 64 x), 256 threads = 8 warps (2M x 4N),
// warp m64 x n32.  TWO CTAs per SM (3-stage 32KB ring = 96KB, <=128 regs):
// cross-CTA overlap fills each CTA's barrier/staging bubbles.
// Grid (31 ytiles, 62 z, 2 b) = 3844 CTAs -> 296 concurrent, ~13 even waves.
// c < 27: B = x;  c >= 27: B = dx (A rows 0..63 zero -> wm==0 warps skip).
// ---------------------------------------------------------------------------
__global__ __launch_bounds__(256, 2) void conv_mma_kernel(
    const float* __restrict__ bias, float* __restrict__ out)
{
    extern __shared__ __align__(16) char smem[];
    const uint32_t sb = smem_u32(smem);

    const int tid = threadIdx.x;
    const int wid = tid >> 5;
    const int lid = tid & 31;
    const int wm  = wid >> 2;          // M tile 0..1 (rows wm*64..)
    const int wn  = wid & 3;           // N tile 0..3 (cols wn*32..)
    const int g   = lid >> 2;          // 0..7
    const int ct  = lid & 3;           // 0..3

    const int y0 = blockIdx.x * 2;     // 2 output rows per CTA (62 = 31*2)
    const int z0 = blockIdx.y;
    const int b  = blockIdx.z;

    float acc[4][4][4];
    #pragma unroll
    for (int mi = 0; mi < 4; ++mi)
        #pragma unroll
        for (int ni = 0; ni < 4; ++ni)
            #pragma unroll
            for (int j = 0; j < 4; ++j) acc[mi][ni][j] = 0.f;

    // ---- per-thread ldmatrix row indices ----
    const int a_m  = wm * 64 + (lid & 7) + ((lid >> 3) & 1) * 8;  // + mi*16
    const int a_kq = (lid >> 4) & 1;
    const int b_n  = wn * 32 + (lid & 7) + ((lid >> 4) & 1) * 8;  // + q*16
    const int b_kq = (lid >> 3) & 1;

    // ---- hoisted staging offsets (chunk-invariant) ----
    uint32_t bDst[4];
    uint32_t bSrc[4];
    #pragma unroll
    for (int it = 0; it < 4; ++it) {
        const int i  = tid + it * 256;     // 0..1023
        const int n  = i >> 3;             // 0..127
        const int c8 = i & 7;
        bDst[it] = (uint32_t)(A_BYTES + n * 128 + ((c8 ^ (n & 7)) << 4));
        bSrc[it] = (uint32_t)((((n >> 6) * 64 + (n & 63)) * 128) + c8 * 16);
    }
    const int rb0 = ((b * 64 + z0) * 64 + y0) * 64;
    const char* xB  = (const char*)g_xTh  + (size_t)rb0 * 128;
    const char* dxB = (const char*)g_dxTh + (size_t)rb0 * 128;
    const char* aBaseX  = (const char*)g_Ah + (size_t)(b * 2)     * KTAPS * A_BYTES;
    const char* aBaseDX = (const char*)g_Ah + (size_t)(b * 2 + 1) * KTAPS * A_BYTES;

    // ---- staging: chunk c into ring slot s ----
    auto stage = [&](int c, int s) {
        const int kind = (c >= KTAPS) ? 1 : 0;
        const int t    = c - (kind ? KTAPS : 0);
        const int dz   = t / 9;
        const int r1   = t - dz * 9;
        const int dyy  = r1 / 3;
        const int dxx  = r1 - dyy * 3;
        const uint32_t d = sb + s * STAGE;
        // A tile (pre-swizzled, linear copy); dx-chunks: rows 0..63 unused
        const char* srcA = (kind ? aBaseDX : aBaseX) + (size_t)t * A_BYTES;
        const uint32_t aOff = (uint32_t)tid * 16;
        if (!kind) {
            cp_async16(d + aOff,        srcA + aOff);
            cp_async16(d + aOff + 4096, srcA + aOff + 4096);
        }
        cp_async16(d + aOff + 8192,  srcA + aOff + 8192);
        cp_async16(d + aOff + 12288, srcA + aOff + 12288);
        // B tile: im2col gather with hoisted offsets (128 rows x 128B)
        const char* srcB = (kind ? dxB : xB) + (size_t)(dz * 4096 + dyy * 64 + dxx) * 128;
        #pragma unroll
        for (int it = 0; it < 4; ++it)
            cp_async16(d + bDst[it], srcB + bSrc[it]);
    };

    // ---- compute one chunk from ring slot s ----
    auto compute = [&](int s) {
        const uint32_t As = sb + s * STAGE;
        const uint32_t Bs = As + A_BYTES;
        #pragma unroll
        for (int ks = 0; ks < 4; ++ks) {
            const int kq_a = ks * 2 + a_kq;
            const int kq_b = ks * 2 + b_kq;
            uint32_t a[4][4];
            #pragma unroll
            for (int mi = 0; mi < 4; ++mi) {
                const int m = a_m + mi * 16;
                LDMATRIX_X4(a[mi][0], a[mi][1], a[mi][2], a[mi][3],
                            As + m * 128 + ((kq_a ^ (m & 7)) << 4));
            }
            uint32_t bq[2][4];
            #pragma unroll
            for (int q = 0; q < 2; ++q) {
                const int n = b_n + q * 16;
                LDMATRIX_X4(bq[q][0], bq[q][1], bq[q][2], bq[q][3],
                            Bs + n * 128 + ((kq_b ^ (n & 7)) << 4));
            }
            #pragma unroll
            for (int mi = 0; mi < 4; ++mi)
                #pragma unroll
                for (int q = 0; q < 2; ++q) {
                    mma_f16(acc[mi][2 * q + 0], a[mi], &bq[q][0]);
                    mma_f16(acc[mi][2 * q + 1], a[mi], &bq[q][2]);
                }
        }
    };

    // ---- prologue: fill 2 of 3 stages ----
    stage(0, 0); asm volatile("cp.async.commit_group;" ::: "memory");
    stage(1, 1); asm volatile("cp.async.commit_group;" ::: "memory");

    int s0i = 0;                        // slot of chunk c
    int s2i = 2;                        // slot of chunk c+2
    // ---- x-chunks: all 8 warps compute ----
    for (int c = 0; c < KTAPS; ++c) {
        asm volatile("cp.async.wait_group %0;" :: "n"(NSTAGE - 2) : "memory");
        __syncthreads();
        stage(c + 2, s2i);              // c+2 <= 28 < 54, always valid
        asm volatile("cp.async.commit_group;" ::: "memory");
        compute(s0i);
        if (++s0i == NSTAGE) s0i = 0;
        if (++s2i == NSTAGE) s2i = 0;
    }
    // ---- dx-chunks: wm==0 warps only stage/sync ----
    for (int c = KTAPS; c < NCHUNK; ++c) {
        asm volatile("cp.async.wait_group %0;" :: "n"(NSTAGE - 2) : "memory");
        __syncthreads();
        if (c + 2 < NCHUNK) stage(c + 2, s2i);
        asm volatile("cp.async.commit_group;" ::: "memory");
        if (wm == 1) compute(s0i);
        if (++s0i == NSTAGE) s0i = 0;
        if (++s2i == NSTAGE) s2i = 0;
    }

    // ---- epilogue ----
    const size_t NOUT   = (size_t)DOUT * DOUT * DOUT;
    const size_t dy_off = (size_t)B_ * COUT * NOUT;
    const int m_base = wm * 64;
    const int n_base = wn * 32;

    #pragma unroll
    for (int mi = 0; mi < 4; ++mi) {
        #pragma unroll
        for (int h = 0; h < 2; ++h) {
            const int m  = m_base + mi * 16 + h * 8 + g;
            const bool isy = (m < 64);
            const int co = m & 63;
            const float bv = isy ? bias[co] : 0.f;
            const size_t outadd = isy ? 0 : dy_off;
            const size_t ob = ((size_t)(b * COUT + co) * DOUT + z0) * DOUT;
            #pragma unroll
            for (int ni = 0; ni < 4; ++ni) {
                const int n  = n_base + ni * 8 + ct * 2;
                const int yo = y0 + (n >> 6);       // < 62 always (31*2 grid)
                const int xo = n & 63;
                const size_t idx = (ob + yo) * DOUT + xo;
                if (xo < DOUT) {
                    out[outadd + idx]     = acc[mi][ni][h * 2 + 0] + bv;
                    out[outadd + idx + 1] = acc[mi][ni][h * 2 + 1] + bv;  // xo even => xo+1 valid
                }
            }
        }
    }
}

// ---------------------------------------------------------------------------
// Launch. Inputs: x, s, dx, style_weight, style_bias, weight, bias.
// Output: concat(y, dy) fp32.
// ---------------------------------------------------------------------------
extern "C" void kernel_launch(void* const* d_in, const int* in_sizes, int n_in,
                              void* d_out, int out_size)
{
    const float* x    = (const float*)d_in[0];
    const float* s    = (const float*)d_in[1];
    const float* dx   = (const float*)d_in[2];
    const float* sw   = (const float*)d_in[3];
    const float* sb   = (const float*)d_in[4];
    const float* w    = (const float*)d_in[5];
    const float* bias = (const float*)d_in[6];
    float* out = (float*)d_out;

    cudaFuncSetAttribute(conv_mma_kernel, cudaFuncAttributeMaxDynamicSharedMemorySize, SMEM_DYN);

    prep_kernel<<<B_ * COUT, 256>>>(s, sw, sb, w);
    pack_kernel<<<B_ * 2 * KTAPS, 256>>>();
    transpose_kernel<<<dim3(64, 64, B_), dim3(32, 8)>>>(x, dx);
    conv_mma_kernel<<<dim3(31, 62, B_), 256, SMEM_DYN>>>(bias, out);
}